// round 13
// baseline (speedup 1.0000x reference)
#include <cuda_runtime.h>
#include <cuda_fp16.h>
#include <math.h>
#include <stdint.h>

// Problem constants (B=4, S=2048, H=128, NH=8)
#define HB 4
#define SEQ 2048
#define HD 128
#define NH 8
#define HEADS (HB * NH)              // 32
#define HEADELEMS (SEQ * HD)         // 262144

// fp16 staging buffers (uint32 = half2 words). Allocation-free device globals.
__device__ uint32_t g_xh[8192 * 64];          // x, chunk-interleaved rows
__device__ uint32_t g_wh[24 * 32 * 256];      // qkv weights, row-pair per 128-col block
__device__ uint32_t g_ph[8 * 32 * 256];       // proj weights, row-pair per 128-row block
__device__ uint32_t g_qh[HEADS * 2048 * 64];  // Q (scale*log2e pre-folded)
__device__ uint32_t g_kh[HEADS * 2048 * 64];  // K
__device__ uint32_t g_vp[HEADS * 2048 * 64];  // V plain fp16 rows
__device__ uint32_t g_vh[HEADS * 32 * 16 * 256]; // V row-pair per 64-row block
__device__ uint32_t g_oh[8192 * 512];         // O, interleaved rows

__device__ __forceinline__ uint32_t f2h2(float lo, float hi) {
    __half2 h = __floats2half2_rn(lo, hi);
    return *reinterpret_cast<uint32_t*>(&h);
}

__device__ __forceinline__ void mma_f16(float c[4],
    uint32_t a0, uint32_t a1, uint32_t a2, uint32_t a3,
    uint32_t b0, uint32_t b1)
{
    asm volatile(
        "mma.sync.aligned.m16n8k16.row.col.f32.f16.f16.f32 "
        "{%0,%1,%2,%3}, {%4,%5,%6,%7}, {%8,%9}, {%0,%1,%2,%3};\n"
        : "+f"(c[0]), "+f"(c[1]), "+f"(c[2]), "+f"(c[3])
        : "r"(a0), "r"(a1), "r"(a2), "r"(a3), "r"(b0), "r"(b1));
}

// 16 consecutive floats -> 8 half2 words stored [w0,w4,w1,w5,w2,w6,w3,w7];
// uint2 read at word 2*c4 yields {w[c4], w[c4+4]} = the fp16 A-fragment pair.
#define STORE_CHUNK(dst, A, B_, C_, D_)                                         \
    do {                                                                        \
        ((uint4*)(dst))[0] = make_uint4(f2h2((A).x,(A).y),  f2h2((C_).x,(C_).y),\
                                        f2h2((A).z,(A).w),  f2h2((C_).z,(C_).w));\
        ((uint4*)(dst))[1] = make_uint4(f2h2((B_).x,(B_).y), f2h2((D_).x,(D_).y),\
                                        f2h2((B_).z,(B_).w), f2h2((D_).z,(D_).w));\
    } while (0)

__device__ __forceinline__ void cp_async16(uint32_t* smem_dst, const uint32_t* gsrc) {
    uint32_t d = (uint32_t)__cvta_generic_to_shared(smem_dst);
    asm volatile("cp.async.cg.shared.global [%0], [%1], 16;\n" :: "r"(d), "l"(gsrc) : "memory");
}
#define CP_COMMIT() asm volatile("cp.async.commit_group;\n" ::: "memory")
#define CP_WAIT0()  asm volatile("cp.async.wait_group 0;\n" ::: "memory")
#define CP_WAIT1()  asm volatile("cp.async.wait_group 1;\n" ::: "memory")

// ---------------------------------------------------------------------------
// One-time format-conversion kernels
// ---------------------------------------------------------------------------
__global__ void convert_x_kernel(const float* __restrict__ x, uint32_t* __restrict__ xh) {
    int id = blockIdx.x * 256 + threadIdx.x;
    int r = id >> 3, ch = id & 7;
    const float* src = &x[r * 128 + ch * 16];
    float4 a = *(const float4*)src;
    float4 b = *(const float4*)(src + 4);
    float4 c = *(const float4*)(src + 8);
    float4 d = *(const float4*)(src + 12);
    STORE_CHUNK(&xh[r * 64 + ch * 8], a, b, c, d);
}

// qkv [128,3072] -> row-pair blocks; Q block scaled by log2(e)/sqrt(128)
__global__ void convert_w_kernel(const float* __restrict__ w, uint32_t* __restrict__ wh) {
    int id = blockIdx.x * 256 + threadIdx.x;
    int n  = id & 127;
    int vr = (id >> 7) & 31;
    int cb = id >> 12;
    int ch = vr >> 2, i = vr & 3;
    int r0 = ch * 16 + 2 * i;
    float s = (cb < 8) ? (0.08838834764831845f * 1.4426950408889634f) : 1.0f;
    int col = cb * 128 + n;
    float v0 = w[(r0    ) * 3072 + col] * s;
    float v1 = w[(r0 + 1) * 3072 + col] * s;
    float v2 = w[(r0 + 8) * 3072 + col] * s;
    float v3 = w[(r0 + 9) * 3072 + col] * s;
    *(uint2*)&wh[cb * 8192 + vr * 256 + 2 * n] = make_uint2(f2h2(v0, v1), f2h2(v2, v3));
}

__global__ void convert_p_kernel(const float* __restrict__ w, uint32_t* __restrict__ ph) {
    int id = blockIdx.x * 256 + threadIdx.x;
    int n  = id & 127;
    int vr = (id >> 7) & 31;
    int kb = id >> 12;
    int ch = vr >> 2, i = vr & 3;
    int r0 = kb * 128 + ch * 16 + 2 * i;
    float v0 = w[(r0    ) * 128 + n];
    float v1 = w[(r0 + 1) * 128 + n];
    float v2 = w[(r0 + 8) * 128 + n];
    float v3 = w[(r0 + 9) * 128 + n];
    *(uint2*)&ph[kb * 8192 + vr * 256 + 2 * n] = make_uint2(f2h2(v0, v1), f2h2(v2, v3));
}

// plain fp16 V rows -> row-pair per 64-row block (coalesced half repack)
__global__ void convert_v_kernel(const uint32_t* __restrict__ vp, uint32_t* __restrict__ vh) {
    int id = blockIdx.x * 256 + threadIdx.x;
    int fc2 = id & 63;
    int vr  = (id >> 6) & 15;
    int bb  = (id >> 10) & 31;
    int hb  = id >> 15;
    int ch = vr >> 2, i = vr & 3;
    int R = bb * 64 + ch * 16 + 2 * i;
    const uint32_t* base = vp + hb * 131072 + R * 64 + fc2;
    uint32_t a = base[0];
    uint32_t b = base[64];
    uint32_t c = base[512];
    uint32_t d = base[576];
    uint4 o;
    o.x = __byte_perm(a, b, 0x5410);
    o.y = __byte_perm(c, d, 0x5410);
    o.z = __byte_perm(a, b, 0x7632);
    o.w = __byte_perm(c, d, 0x7632);
    *(uint4*)&vh[hb * 131072 + bb * 4096 + vr * 256 + 4 * fc2] = o;
}

// ---------------------------------------------------------------------------
// Fused QKV GEMM (round-12 version, unchanged)
// ---------------------------------------------------------------------------
__global__ __launch_bounds__(256, 2)
void f16_gemm_qkv(const uint32_t* __restrict__ A, const uint32_t* __restrict__ Bq,
                  uint32_t* __restrict__ H0, uint32_t* __restrict__ H1,
                  uint32_t* __restrict__ Vp)
{
    extern __shared__ uint32_t smg[];
    uint32_t* As0 = smg;
    uint32_t* As1 = smg + 9216;
    uint32_t* Bs  = smg + 18432;

    const int tid  = threadIdx.x;
    const int lane = tid & 31;
    const int g    = lane >> 2;
    const int c4   = lane & 3;
    const int mw   = (tid >> 5) * 16;
    const int bx   = blockIdx.x;
    const int byr  = blockIdx.y;
    const int seg  = bx >> 3;
    const int m    = bx & 7;

    #pragma unroll
    for (int p = 0; p < 8; p++) {
        int cid = p * 256 + tid;
        int vr = cid >> 6, w = cid & 63;
        cp_async16(&Bs[vr * 264 + w * 4], Bq + bx * 8192 + vr * 256 + w * 4);
    }
    #pragma unroll
    for (int p = 0; p < 8; p++) {
        int cid = p * 256 + tid;
        int r = cid >> 4, w4 = cid & 15;
        cp_async16(&As0[r * 72 + w4 * 4], A + (byr * 512 + r) * 64 + w4 * 4);
    }
    CP_COMMIT();
    #pragma unroll
    for (int p = 0; p < 8; p++) {
        int cid = p * 256 + tid;
        int r = cid >> 4, w4 = cid & 15;
        cp_async16(&As1[r * 72 + w4 * 4], A + (byr * 512 + 128 + r) * 64 + w4 * 4);
    }
    CP_COMMIT();

    #pragma unroll
    for (int it = 0; it < 4; it++) {
        CP_WAIT1();
        __syncthreads();
        const uint32_t* Asb = (it & 1) ? As1 : As0;

        float acc[16][4];
        #pragma unroll
        for (int t = 0; t < 16; t++)
            #pragma unroll
            for (int j = 0; j < 4; j++) acc[t][j] = 0.0f;

        #pragma unroll
        for (int kc = 0; kc < 8; kc++) {
            uint2 aa = *(const uint2*)&Asb[(mw + g)     * 72 + kc * 8 + 2 * c4];
            uint2 ab = *(const uint2*)&Asb[(mw + g + 8) * 72 + kc * 8 + 2 * c4];
            #pragma unroll
            for (int t = 0; t < 16; t++) {
                uint2 bb = *(const uint2*)&Bs[(kc * 4 + c4) * 264 + 2 * (t * 8 + g)];
                mma_f16(acc[t], aa.x, ab.x, aa.y, ab.y, bb.x, bb.y);
            }
        }
        __syncthreads();

        if (it + 2 < 4) {
            uint32_t* Asn = (it & 1) ? As1 : As0;
            #pragma unroll
            for (int p = 0; p < 8; p++) {
                int cid = p * 256 + tid;
                int r = cid >> 4, w4 = cid & 15;
                cp_async16(&Asn[r * 72 + w4 * 4],
                           A + (byr * 512 + (it + 2) * 128 + r) * 64 + w4 * 4);
            }
        }
        CP_COMMIT();

        const int r0 = byr * 512 + it * 128 + mw + g;
        const int r1 = r0 + 8;
        if (seg < 2) {
            uint32_t* H = seg ? H1 : H0;
            const int hb = r0 >> 8;
            const int t0 = (r0 & 255) * 8 + m;
            const int t1 = (r1 & 255) * 8 + m;
            #pragma unroll
            for (int t = 0; t < 16; t++) {
                const int pos = (t >> 1) * 8 + 2 * c4 + (t & 1);
                H[hb * 131072 + t0 * 64 + pos] = f2h2(acc[t][0], acc[t][1]);
                H[hb * 131072 + t1 * 64 + pos] = f2h2(acc[t][2], acc[t][3]);
            }
        } else {
            const int hb = r0 >> 8;
            const int s0 = (r0 & 255) * 8 + m;
            const int s1 = (r1 & 255) * 8 + m;
            uint32_t* VPb = Vp + hb * 131072;
            #pragma unroll
            for (int t = 0; t < 16; t++) {
                VPb[s0 * 64 + t * 4 + c4] = f2h2(acc[t][0], acc[t][1]);
                VPb[s1 * 64 + t * 4 + c4] = f2h2(acc[t][2], acc[t][3]);
            }
        }
    }
}

// ---------------------------------------------------------------------------
// Projection GEMM (round-12 version, unchanged)
// ---------------------------------------------------------------------------
__global__ __launch_bounds__(256, 2)
void f16_gemm_proj(const uint32_t* __restrict__ A, const uint32_t* __restrict__ Bq,
                   float* __restrict__ Cf)
{
    extern __shared__ uint32_t smg[];
    uint32_t* AsB[2] = { smg, smg + 9216 };
    uint32_t* BsB[2] = { smg + 18432, smg + 18432 + 4352 };

    const int tid  = threadIdx.x;
    const int lane = tid & 31;
    const int g    = lane >> 2;
    const int c4   = lane & 3;
    const int mw   = (tid >> 5) * 16;
    const int bx   = blockIdx.x;
    const int row0 = blockIdx.y * 128;

    auto loadA = [&](uint32_t* dst, int kt) {
        #pragma unroll
        for (int p = 0; p < 8; p++) {
            int cid = p * 256 + tid;
            int r = cid >> 4, w4 = cid & 15;
            cp_async16(&dst[r * 72 + w4 * 4],
                       A + (long)(row0 + r) * 512 + kt * 64 + w4 * 4);
        }
    };
    auto loadB = [&](uint32_t* dst, int kt) {
        #pragma unroll
        for (int p = 0; p < 4; p++) {
            int cid = p * 256 + tid;
            int vr = cid >> 5, w = cid & 31;
            cp_async16(&dst[vr * 136 + w * 4],
                       Bq + kt * 8192 + vr * 256 + bx * 128 + w * 4);
        }
    };

    loadA(AsB[0], 0); loadB(BsB[0], 0); CP_COMMIT();
    loadA(AsB[1], 1); loadB(BsB[1], 1); CP_COMMIT();

    float acc[8][4];
    #pragma unroll
    for (int t = 0; t < 8; t++)
        #pragma unroll
        for (int j = 0; j < 4; j++) acc[t][j] = 0.0f;

    #pragma unroll
    for (int kt = 0; kt < 8; kt++) {
        CP_WAIT1();
        __syncthreads();
        const uint32_t* As = AsB[kt & 1];
        const uint32_t* Bs = BsB[kt & 1];

        #pragma unroll
        for (int kc = 0; kc < 8; kc++) {
            uint2 aa = *(const uint2*)&As[(mw + g)     * 72 + kc * 8 + 2 * c4];
            uint2 ab = *(const uint2*)&As[(mw + g + 8) * 72 + kc * 8 + 2 * c4];
            #pragma unroll
            for (int t = 0; t < 8; t++) {
                uint2 bb = *(const uint2*)&Bs[(kc * 4 + c4) * 136 + 2 * (t * 8 + g)];
                mma_f16(acc[t], aa.x, ab.x, aa.y, ab.y, bb.x, bb.y);
            }
        }
        __syncthreads();

        if (kt + 2 < 8) { loadA(AsB[kt & 1], kt + 2); loadB(BsB[kt & 1], kt + 2); }
        CP_COMMIT();
    }

    const int r0 = row0 + mw + g;
    const int r1 = r0 + 8;
    #pragma unroll
    for (int t = 0; t < 8; t++) {
        const int col = bx * 64 + t * 8 + 2 * c4;
        *(float2*)&Cf[r0 * 128 + col] = make_float2(acc[t][0], acc[t][1]);
        *(float2*)&Cf[r1 * 128 + col] = make_float2(acc[t][2], acc[t][3]);
    }
}

// ---------------------------------------------------------------------------
// FP16 flash attention v6: P NEVER touches smem — the S accumulator fragment
// (rows g/g+8 x cols t*8+2c4) IS the PV A-operand fragment after f2h2 packing
// (FA2 C->A reuse). Softmax in base-2 logit domain (log2e folded into Wq).
// smem = Q 9216 + K 4608 + 2xV 8448 = 22272 words = 89,088 B -> 2 CTAs/SM.
// ---------------------------------------------------------------------------
#define FLDQ 72
#define FLDK 72
#define FLDV 264
#define FQS  0
#define FKS  (128 * FLDQ)            // 9216
#define FVS0 (FKS + 64 * FLDK)       // 13824
#define FVS1 (FVS0 + 16 * FLDV)      // 18048
#define FSMEMW (FVS1 + 16 * FLDV)    // 22272

__global__ __launch_bounds__(256, 2)
void flash_f16_kernel(const uint32_t* __restrict__ qh, const uint32_t* __restrict__ kh,
                      const uint32_t* __restrict__ vh, uint32_t* __restrict__ oh)
{
    extern __shared__ uint32_t sm[];
    uint32_t* Qs = sm + FQS;
    uint32_t* Ks = sm + FKS;

    const int tid  = threadIdx.x;
    const int lane = tid & 31;
    const int g    = lane >> 2;
    const int c4   = lane & 3;
    const int mw   = (tid >> 5) * 16;

    const int hb = blockIdx.x;
    const int qt = (int)gridDim.y - 1 - (int)blockIdx.y;
    const int q0 = qt * 128;

    const uint32_t* QH = qh + hb * 131072;
    const uint32_t* KH = kh + hb * 131072;
    const uint32_t* VH = vh + hb * 131072;

    const int nkv = (q0 + 128) / 64;

    #pragma unroll
    for (int p = 0; p < 8; p++) {
        int cid = p * 256 + tid;
        int r = cid >> 4, w4 = cid & 15;
        cp_async16(&Qs[r * FLDQ + w4 * 4], QH + (q0 + r) * 64 + w4 * 4);
    }
    #pragma unroll
    for (int p = 0; p < 4; p++) {
        int cid = p * 256 + tid;
        int r = cid >> 4, w4 = cid & 15;
        cp_async16(&Ks[r * FLDK + w4 * 4], KH + r * 64 + w4 * 4);
    }
    #pragma unroll
    for (int p = 0; p < 4; p++) {
        int cid = p * 256 + tid;
        int vr = cid >> 6, w = cid & 63;
        cp_async16(&sm[FVS0 + vr * FLDV + w * 4], VH + vr * 256 + w * 4);
    }
    CP_COMMIT(); CP_WAIT0();
    __syncthreads();

    float of[16][4];
    #pragma unroll
    for (int t = 0; t < 16; t++)
        #pragma unroll
        for (int j = 0; j < 4; j++) of[t][j] = 0.0f;
    float m0 = -INFINITY, m1 = -INFINITY, l0 = 0.0f, l1 = 0.0f;

    for (int kt = 0; kt < nkv; kt++) {
        const bool more = (kt + 1 < nkv);
        const uint32_t* Vb = sm + ((kt & 1) ? FVS1 : FVS0);

        // ---- S2 = Q2 @ K^T (base-2 logits; scale*log2e pre-folded) ----
        float sf[8][4];
        #pragma unroll
        for (int t = 0; t < 8; t++)
            #pragma unroll
            for (int j = 0; j < 4; j++) sf[t][j] = 0.0f;

        #pragma unroll
        for (int k = 0; k < 8; k++) {
            uint2 qa = *(const uint2*)&Qs[(mw + g)     * FLDQ + k * 8 + 2 * c4];
            uint2 qb = *(const uint2*)&Qs[(mw + g + 8) * FLDQ + k * 8 + 2 * c4];
            #pragma unroll
            for (int t = 0; t < 8; t++) {
                uint2 kb = *(const uint2*)&Ks[(t * 8 + g) * FLDK + k * 8 + 2 * c4];
                mma_f16(sf[t], qa.x, qb.x, qa.y, qb.y, kb.x, kb.y);
            }
        }

        if (kt >= nkv - 2) {
            const int k0 = kt * 64;
            const int r0 = q0 + mw + g;
            const int r1 = r0 + 8;
            #pragma unroll
            for (int t = 0; t < 8; t++) {
                const int cg0 = k0 + t * 8 + c4 * 2;
                if (cg0     > r0) sf[t][0] = -INFINITY;
                if (cg0 + 1 > r0) sf[t][1] = -INFINITY;
                if (cg0     > r1) sf[t][2] = -INFINITY;
                if (cg0 + 1 > r1) sf[t][3] = -INFINITY;
            }
        }

        __syncthreads();   // all warps done reading Ks

        if (more) {
            const int kn = (kt + 1) * 64;
            uint32_t* Vn = sm + (((kt + 1) & 1) ? FVS1 : FVS0);
            #pragma unroll
            for (int p = 0; p < 4; p++) {
                int cid = p * 256 + tid;
                int r = cid >> 4, w4 = cid & 15;
                cp_async16(&Ks[r * FLDK + w4 * 4], KH + (kn + r) * 64 + w4 * 4);
            }
            #pragma unroll
            for (int p = 0; p < 4; p++) {
                int cid = p * 256 + tid;
                int vr = cid >> 6, w = cid & 63;
                cp_async16(&Vn[vr * FLDV + w * 4],
                           VH + (kt + 1) * 4096 + vr * 256 + w * 4);
            }
            CP_COMMIT();
        }

        // ---- online softmax (base 2, quad-local reduce) ----
        float mx0 = -INFINITY, mx1 = -INFINITY;
        #pragma unroll
        for (int t = 0; t < 8; t++) {
            mx0 = fmaxf(mx0, fmaxf(sf[t][0], sf[t][1]));
            mx1 = fmaxf(mx1, fmaxf(sf[t][2], sf[t][3]));
        }
        mx0 = fmaxf(mx0, __shfl_xor_sync(0xffffffffu, mx0, 1));
        mx0 = fmaxf(mx0, __shfl_xor_sync(0xffffffffu, mx0, 2));
        mx1 = fmaxf(mx1, __shfl_xor_sync(0xffffffffu, mx1, 1));
        mx1 = fmaxf(mx1, __shfl_xor_sync(0xffffffffu, mx1, 2));

        const float mn0 = fmaxf(m0, mx0);
        const float mn1 = fmaxf(m1, mx1);
        const float al0 = exp2f(m0 - mn0);
        const float al1 = exp2f(m1 - mn1);

        float s0 = 0.0f, s1 = 0.0f;
        #pragma unroll
        for (int t = 0; t < 8; t++) {
            sf[t][0] = exp2f(sf[t][0] - mn0);
            sf[t][1] = exp2f(sf[t][1] - mn0);
            sf[t][2] = exp2f(sf[t][2] - mn1);
            sf[t][3] = exp2f(sf[t][3] - mn1);
            s0 += sf[t][0] + sf[t][1];
            s1 += sf[t][2] + sf[t][3];
        }
        s0 += __shfl_xor_sync(0xffffffffu, s0, 1);
        s0 += __shfl_xor_sync(0xffffffffu, s0, 2);
        s1 += __shfl_xor_sync(0xffffffffu, s1, 1);
        s1 += __shfl_xor_sync(0xffffffffu, s1, 2);

        l0 = l0 * al0 + s0;  m0 = mn0;
        l1 = l1 * al1 + s1;  m1 = mn1;

        #pragma unroll
        for (int t = 0; t < 16; t++) {
            of[t][0] *= al0; of[t][1] *= al0;
            of[t][2] *= al1; of[t][3] *= al1;
        }

        // ---- O += P @ V : P directly from S-accumulator registers ----
        #pragma unroll
        for (int kc = 0; kc < 4; kc++) {
            uint32_t a0 = f2h2(sf[2*kc  ][0], sf[2*kc  ][1]);
            uint32_t a1 = f2h2(sf[2*kc  ][2], sf[2*kc  ][3]);
            uint32_t a2 = f2h2(sf[2*kc+1][0], sf[2*kc+1][1]);
            uint32_t a3 = f2h2(sf[2*kc+1][2], sf[2*kc+1][3]);
            #pragma unroll
            for (int t = 0; t < 16; t++) {
                uint2 vb = *(const uint2*)&Vb[(kc * 4 + c4) * FLDV + 2 * (t * 8 + g)];
                mma_f16(of[t], a0, a1, a2, a3, vb.x, vb.y);
            }
        }

        CP_WAIT0();
        __syncthreads();
    }

    const float inv0 = 1.0f / l0;
    const float inv1 = 1.0f / l1;
    const int r0f = q0 + mw + g;
    const int r1f = r0f + 8;
    const int grow0 = hb * 256 + (r0f >> 3);
    const int grow1 = hb * 256 + (r1f >> 3);
    const int cb0 = (r0f & 7) * 8;
    const int cb1 = (r1f & 7) * 8;
    #pragma unroll
    for (int t = 0; t < 16; t++) {
        const int sub = 2 * c4 + (t & 1);
        oh[grow0 * 512 + (cb0 + (t >> 1)) * 8 + sub] = f2h2(of[t][0] * inv0, of[t][1] * inv0);
        oh[grow1 * 512 + (cb1 + (t >> 1)) * 8 + sub] = f2h2(of[t][2] * inv1, of[t][3] * inv1);
    }
}

// ---------------------------------------------------------------------------
// Launch
// ---------------------------------------------------------------------------
extern "C" void kernel_launch(void* const* d_in, const int* in_sizes, int n_in,
                              void* d_out, int out_size)
{
    const float* x    = (const float*)d_in[0];
    const float* qkv  = (const float*)d_in[1];
    const float* proj = (const float*)d_in[2];
    float* out = (float*)d_out;

    uint32_t *xh, *wh, *ph, *qh, *kh, *vp, *vh, *oh;
    cudaGetSymbolAddress((void**)&xh, g_xh);
    cudaGetSymbolAddress((void**)&wh, g_wh);
    cudaGetSymbolAddress((void**)&ph, g_ph);
    cudaGetSymbolAddress((void**)&qh, g_qh);
    cudaGetSymbolAddress((void**)&kh, g_kh);
    cudaGetSymbolAddress((void**)&vp, g_vp);
    cudaGetSymbolAddress((void**)&vh, g_vh);
    cudaGetSymbolAddress((void**)&oh, g_oh);

    convert_x_kernel<<<256, 256>>>(x, xh);
    convert_w_kernel<<<384, 256>>>(qkv, wh);
    convert_p_kernel<<<128, 256>>>(proj, ph);

    const int qkv_smem = (2 * 128 * 72 + 32 * 264) * (int)sizeof(uint32_t);
    cudaFuncSetAttribute(f16_gemm_qkv,
                         cudaFuncAttributeMaxDynamicSharedMemorySize, qkv_smem);
    f16_gemm_qkv<<<dim3(24, 16), 256, qkv_smem>>>(xh, wh, qh, kh, vp);

    convert_v_kernel<<<4096, 256>>>(vp, vh);

    const int flash_smem = FSMEMW * (int)sizeof(uint32_t);  // 89,088
    cudaFuncSetAttribute(flash_f16_kernel,
                         cudaFuncAttributeMaxDynamicSharedMemorySize, flash_smem);
    flash_f16_kernel<<<dim3(HEADS, SEQ / 128), 256, flash_smem>>>(qh, kh, vh, oh);

    const int proj_smem = (2 * 128 * 72 + 2 * 32 * 136) * (int)sizeof(uint32_t);
    cudaFuncSetAttribute(f16_gemm_proj,
                         cudaFuncAttributeMaxDynamicSharedMemorySize, proj_smem);
    f16_gemm_proj<<<dim3(2, 64), 256, proj_smem>>>(oh, ph, out);
}

// round 15
// speedup vs baseline: 1.0548x; 1.0548x over previous
#include <cuda_runtime.h>
#include <cuda_fp16.h>
#include <math.h>
#include <stdint.h>

// Problem constants (B=4, S=2048, H=128, NH=8)
#define HB 4
#define SEQ 2048
#define HD 128
#define NH 8
#define HEADS (HB * NH)              // 32
#define HEADELEMS (SEQ * HD)         // 262144

// fp16 staging buffers (uint32 = half2 words). Allocation-free device globals.
__device__ uint32_t g_xh[8192 * 64];          // x, chunk-interleaved rows
__device__ uint32_t g_wh[24 * 32 * 256];      // qkv weights, row-pair per 128-col block
__device__ uint32_t g_ph[8 * 32 * 256];       // proj weights, row-pair per 128-row block
__device__ uint32_t g_qh[HEADS * 2048 * 64];  // Q (scale*log2e pre-folded)
__device__ uint32_t g_kh[HEADS * 2048 * 64];  // K
__device__ uint32_t g_vp[HEADS * 2048 * 64];  // V plain fp16 rows
__device__ uint32_t g_vh[HEADS * 32 * 16 * 256]; // V row-pair per 64-row block
__device__ uint32_t g_oh[8192 * 512];         // O, interleaved rows

__device__ __forceinline__ uint32_t f2h2(float lo, float hi) {
    __half2 h = __floats2half2_rn(lo, hi);
    return *reinterpret_cast<uint32_t*>(&h);
}

__device__ __forceinline__ void mma_f16(float c[4],
    uint32_t a0, uint32_t a1, uint32_t a2, uint32_t a3,
    uint32_t b0, uint32_t b1)
{
    asm volatile(
        "mma.sync.aligned.m16n8k16.row.col.f32.f16.f16.f32 "
        "{%0,%1,%2,%3}, {%4,%5,%6,%7}, {%8,%9}, {%0,%1,%2,%3};\n"
        : "+f"(c[0]), "+f"(c[1]), "+f"(c[2]), "+f"(c[3])
        : "r"(a0), "r"(a1), "r"(a2), "r"(a3), "r"(b0), "r"(b1));
}

#define STORE_CHUNK(dst, A, B_, C_, D_)                                         \
    do {                                                                        \
        ((uint4*)(dst))[0] = make_uint4(f2h2((A).x,(A).y),  f2h2((C_).x,(C_).y),\
                                        f2h2((A).z,(A).w),  f2h2((C_).z,(C_).w));\
        ((uint4*)(dst))[1] = make_uint4(f2h2((B_).x,(B_).y), f2h2((D_).x,(D_).y),\
                                        f2h2((B_).z,(B_).w), f2h2((D_).z,(D_).w));\
    } while (0)

__device__ __forceinline__ void cp_async16(uint32_t* smem_dst, const uint32_t* gsrc) {
    uint32_t d = (uint32_t)__cvta_generic_to_shared(smem_dst);
    asm volatile("cp.async.cg.shared.global [%0], [%1], 16;\n" :: "r"(d), "l"(gsrc) : "memory");
}
#define CP_COMMIT() asm volatile("cp.async.commit_group;\n" ::: "memory")
#define CP_WAIT0()  asm volatile("cp.async.wait_group 0;\n" ::: "memory")
#define CP_WAIT1()  asm volatile("cp.async.wait_group 1;\n" ::: "memory")

// ---------------------------------------------------------------------------
// Merged one-time format conversion: blocks [0,256) x, [256,640) w, [640,768) p
// ---------------------------------------------------------------------------
__global__ void convert_all(const float* __restrict__ x, const float* __restrict__ w,
                            const float* __restrict__ p,
                            uint32_t* __restrict__ xh, uint32_t* __restrict__ wh,
                            uint32_t* __restrict__ ph)
{
    int blk = blockIdx.x;
    if (blk < 256) {
        int id = blk * 256 + threadIdx.x;        // x: 65536 ids
        int r = id >> 3, ch = id & 7;
        const float* src = &x[r * 128 + ch * 16];
        float4 a = *(const float4*)src;
        float4 b = *(const float4*)(src + 4);
        float4 c = *(const float4*)(src + 8);
        float4 d = *(const float4*)(src + 12);
        STORE_CHUNK(&xh[r * 64 + ch * 8], a, b, c, d);
    } else if (blk < 640) {
        int id = (blk - 256) * 256 + threadIdx.x;  // w: 98304 ids
        int n  = id & 127;
        int vr = (id >> 7) & 31;
        int cb = id >> 12;
        int ch = vr >> 2, i = vr & 3;
        int r0 = ch * 16 + 2 * i;
        float s = (cb < 8) ? (0.08838834764831845f * 1.4426950408889634f) : 1.0f;
        int col = cb * 128 + n;
        float v0 = w[(r0    ) * 3072 + col] * s;
        float v1 = w[(r0 + 1) * 3072 + col] * s;
        float v2 = w[(r0 + 8) * 3072 + col] * s;
        float v3 = w[(r0 + 9) * 3072 + col] * s;
        *(uint2*)&wh[cb * 8192 + vr * 256 + 2 * n] = make_uint2(f2h2(v0, v1), f2h2(v2, v3));
    } else {
        int id = (blk - 640) * 256 + threadIdx.x;  // p: 32768 ids
        int n  = id & 127;
        int vr = (id >> 7) & 31;
        int kb = id >> 12;
        int ch = vr >> 2, i = vr & 3;
        int r0 = kb * 128 + ch * 16 + 2 * i;
        float v0 = p[(r0    ) * 128 + n];
        float v1 = p[(r0 + 1) * 128 + n];
        float v2 = p[(r0 + 8) * 128 + n];
        float v3 = p[(r0 + 9) * 128 + n];
        *(uint2*)&ph[kb * 8192 + vr * 256 + 2 * n] = make_uint2(f2h2(v0, v1), f2h2(v2, v3));
    }
}

// plain fp16 V rows -> row-pair per 64-row block (coalesced half repack)
__global__ void convert_v_kernel(const uint32_t* __restrict__ vp, uint32_t* __restrict__ vh) {
    int id = blockIdx.x * 256 + threadIdx.x;
    int fc2 = id & 63;
    int vr  = (id >> 6) & 15;
    int bb  = (id >> 10) & 31;
    int hb  = id >> 15;
    int ch = vr >> 2, i = vr & 3;
    int R = bb * 64 + ch * 16 + 2 * i;
    const uint32_t* base = vp + hb * 131072 + R * 64 + fc2;
    uint32_t a = base[0];
    uint32_t b = base[64];
    uint32_t c = base[512];
    uint32_t d = base[576];
    uint4 o;
    o.x = __byte_perm(a, b, 0x5410);
    o.y = __byte_perm(c, d, 0x5410);
    o.z = __byte_perm(a, b, 0x7632);
    o.w = __byte_perm(c, d, 0x7632);
    *(uint4*)&vh[hb * 131072 + bb * 4096 + vr * 256 + 4 * fc2] = o;
}

// ---------------------------------------------------------------------------
// Fused QKV GEMM v4: BM=64 x BN=128 tiles, 128 threads, 4 CTAs/SM.
// grid (24, 128) = 3072 CTAs (~5.2 waves) for occupancy-based latency hiding.
// A: chunk-interleaved rows (ld 72). B: row-pair block (32 x 264).
// smem 13,056 words = 52,224 B. Q/K epilogue uses paired uint2 stores.
// ---------------------------------------------------------------------------
__global__ __launch_bounds__(128, 4)
void f16_gemm_qkv(const uint32_t* __restrict__ A, const uint32_t* __restrict__ Bq,
                  uint32_t* __restrict__ H0, uint32_t* __restrict__ H1,
                  uint32_t* __restrict__ Vp)
{
    extern __shared__ uint32_t smg[];
    uint32_t* As = smg;                 // 64 x 72
    uint32_t* Bs = smg + 64 * 72;       // 32 x 264

    const int tid  = threadIdx.x;
    const int lane = tid & 31;
    const int g    = lane >> 2;
    const int c4   = lane & 3;
    const int mw   = (tid >> 5) * 16;   // 4 warps x m16 = 64 rows
    const int bx   = blockIdx.x;        // col block 0..23
    const int by   = blockIdx.y;        // row tile 0..127 (64 rows)
    const int seg  = bx >> 3;
    const int m    = bx & 7;

    // prologue: A (64x128) + B (128x128 row-pair) via cp.async
    #pragma unroll
    for (int p = 0; p < 8; p++) {
        int cid = p * 128 + tid;
        int r = cid >> 4, w4 = cid & 15;
        cp_async16(&As[r * 72 + w4 * 4], A + (by * 64 + r) * 64 + w4 * 4);
    }
    #pragma unroll
    for (int p = 0; p < 16; p++) {
        int cid = p * 128 + tid;
        int vr = cid >> 6, w = cid & 63;
        cp_async16(&Bs[vr * 264 + w * 4], Bq + bx * 8192 + vr * 256 + w * 4);
    }
    CP_COMMIT(); CP_WAIT0();
    __syncthreads();

    float acc[16][4];
    #pragma unroll
    for (int t = 0; t < 16; t++)
        #pragma unroll
        for (int j = 0; j < 4; j++) acc[t][j] = 0.0f;

    #pragma unroll
    for (int kc = 0; kc < 8; kc++) {
        uint2 aa = *(const uint2*)&As[(mw + g)     * 72 + kc * 8 + 2 * c4];
        uint2 ab = *(const uint2*)&As[(mw + g + 8) * 72 + kc * 8 + 2 * c4];
        #pragma unroll
        for (int t = 0; t < 16; t++) {
            uint2 bb = *(const uint2*)&Bs[(kc * 4 + c4) * 264 + 2 * (t * 8 + g)];
            mma_f16(acc[t], aa.x, ab.x, aa.y, ab.y, bb.x, bb.y);
        }
    }

    // epilogue
    const int r0 = by * 64 + mw + g;
    const int r1 = r0 + 8;
    const int hb = r0 >> 8;
    if (seg < 2) {
        uint32_t* H = seg ? H1 : H0;
        uint32_t* row0 = H + hb * 131072 + ((r0 & 255) * 8 + m) * 64;
        uint32_t* row1 = H + hb * 131072 + ((r1 & 255) * 8 + m) * 64;
        #pragma unroll
        for (int c = 0; c < 8; c++) {   // chunk c covers t=2c, 2c+1
            const int pos = c * 8 + 2 * c4;
            *(uint2*)&row0[pos] = make_uint2(f2h2(acc[2*c][0], acc[2*c][1]),
                                             f2h2(acc[2*c+1][0], acc[2*c+1][1]));
            *(uint2*)&row1[pos] = make_uint2(f2h2(acc[2*c][2], acc[2*c][3]),
                                             f2h2(acc[2*c+1][2], acc[2*c+1][3]));
        }
    } else {
        uint32_t* row0 = Vp + hb * 131072 + ((r0 & 255) * 8 + m) * 64;
        uint32_t* row1 = Vp + hb * 131072 + ((r1 & 255) * 8 + m) * 64;
        #pragma unroll
        for (int t = 0; t < 16; t++) {
            row0[t * 4 + c4] = f2h2(acc[t][0], acc[t][1]);
            row1[t * 4 + c4] = f2h2(acc[t][2], acc[t][3]);
        }
    }
}

// ---------------------------------------------------------------------------
// Projection GEMM (round-12 version, unchanged)
// ---------------------------------------------------------------------------
__global__ __launch_bounds__(256, 2)
void f16_gemm_proj(const uint32_t* __restrict__ A, const uint32_t* __restrict__ Bq,
                   float* __restrict__ Cf)
{
    extern __shared__ uint32_t smg[];
    uint32_t* AsB[2] = { smg, smg + 9216 };
    uint32_t* BsB[2] = { smg + 18432, smg + 18432 + 4352 };

    const int tid  = threadIdx.x;
    const int lane = tid & 31;
    const int g    = lane >> 2;
    const int c4   = lane & 3;
    const int mw   = (tid >> 5) * 16;
    const int bx   = blockIdx.x;
    const int row0 = blockIdx.y * 128;

    auto loadA = [&](uint32_t* dst, int kt) {
        #pragma unroll
        for (int p = 0; p < 8; p++) {
            int cid = p * 256 + tid;
            int r = cid >> 4, w4 = cid & 15;
            cp_async16(&dst[r * 72 + w4 * 4],
                       A + (long)(row0 + r) * 512 + kt * 64 + w4 * 4);
        }
    };
    auto loadB = [&](uint32_t* dst, int kt) {
        #pragma unroll
        for (int p = 0; p < 4; p++) {
            int cid = p * 256 + tid;
            int vr = cid >> 5, w = cid & 31;
            cp_async16(&dst[vr * 136 + w * 4],
                       Bq + kt * 8192 + vr * 256 + bx * 128 + w * 4);
        }
    };

    loadA(AsB[0], 0); loadB(BsB[0], 0); CP_COMMIT();
    loadA(AsB[1], 1); loadB(BsB[1], 1); CP_COMMIT();

    float acc[8][4];
    #pragma unroll
    for (int t = 0; t < 8; t++)
        #pragma unroll
        for (int j = 0; j < 4; j++) acc[t][j] = 0.0f;

    #pragma unroll
    for (int kt = 0; kt < 8; kt++) {
        CP_WAIT1();
        __syncthreads();
        const uint32_t* As = AsB[kt & 1];
        const uint32_t* Bs = BsB[kt & 1];

        #pragma unroll
        for (int kc = 0; kc < 8; kc++) {
            uint2 aa = *(const uint2*)&As[(mw + g)     * 72 + kc * 8 + 2 * c4];
            uint2 ab = *(const uint2*)&As[(mw + g + 8) * 72 + kc * 8 + 2 * c4];
            #pragma unroll
            for (int t = 0; t < 8; t++) {
                uint2 bb = *(const uint2*)&Bs[(kc * 4 + c4) * 136 + 2 * (t * 8 + g)];
                mma_f16(acc[t], aa.x, ab.x, aa.y, ab.y, bb.x, bb.y);
            }
        }
        __syncthreads();

        if (kt + 2 < 8) { loadA(AsB[kt & 1], kt + 2); loadB(BsB[kt & 1], kt + 2); }
        CP_COMMIT();
    }

    const int r0 = row0 + mw + g;
    const int r1 = r0 + 8;
    #pragma unroll
    for (int t = 0; t < 8; t++) {
        const int col = bx * 64 + t * 8 + 2 * c4;
        *(float2*)&Cf[r0 * 128 + col] = make_float2(acc[t][0], acc[t][1]);
        *(float2*)&Cf[r1 * 128 + col] = make_float2(acc[t][2], acc[t][3]);
    }
}

// ---------------------------------------------------------------------------
// FP16 flash attention (round-13 version, unchanged): P in registers,
// base-2 softmax, cp.async pipeline, 2 CTAs/SM. (At the mma.sync ceiling.)
// ---------------------------------------------------------------------------
#define FLDQ 72
#define FLDK 72
#define FLDV 264
#define FQS  0
#define FKS  (128 * FLDQ)
#define FVS0 (FKS + 64 * FLDK)
#define FVS1 (FVS0 + 16 * FLDV)
#define FSMEMW (FVS1 + 16 * FLDV)

__global__ __launch_bounds__(256, 2)
void flash_f16_kernel(const uint32_t* __restrict__ qh, const uint32_t* __restrict__ kh,
                      const uint32_t* __restrict__ vh, uint32_t* __restrict__ oh)
{
    extern __shared__ uint32_t sm[];
    uint32_t* Qs = sm + FQS;
    uint32_t* Ks = sm + FKS;

    const int tid  = threadIdx.x;
    const int lane = tid & 31;
    const int g    = lane >> 2;
    const int c4   = lane & 3;
    const int mw   = (tid >> 5) * 16;

    const int hb = blockIdx.x;
    const int qt = (int)gridDim.y - 1 - (int)blockIdx.y;
    const int q0 = qt * 128;

    const uint32_t* QH = qh + hb * 131072;
    const uint32_t* KH = kh + hb * 131072;
    const uint32_t* VH = vh + hb * 131072;

    const int nkv = (q0 + 128) / 64;

    #pragma unroll
    for (int p = 0; p < 8; p++) {
        int cid = p * 256 + tid;
        int r = cid >> 4, w4 = cid & 15;
        cp_async16(&Qs[r * FLDQ + w4 * 4], QH + (q0 + r) * 64 + w4 * 4);
    }
    #pragma unroll
    for (int p = 0; p < 4; p++) {
        int cid = p * 256 + tid;
        int r = cid >> 4, w4 = cid & 15;
        cp_async16(&Ks[r * FLDK + w4 * 4], KH + r * 64 + w4 * 4);
    }
    #pragma unroll
    for (int p = 0; p < 4; p++) {
        int cid = p * 256 + tid;
        int vr = cid >> 6, w = cid & 63;
        cp_async16(&sm[FVS0 + vr * FLDV + w * 4], VH + vr * 256 + w * 4);
    }
    CP_COMMIT(); CP_WAIT0();
    __syncthreads();

    float of[16][4];
    #pragma unroll
    for (int t = 0; t < 16; t++)
        #pragma unroll
        for (int j = 0; j < 4; j++) of[t][j] = 0.0f;
    float m0 = -INFINITY, m1 = -INFINITY, l0 = 0.0f, l1 = 0.0f;

    for (int kt = 0; kt < nkv; kt++) {
        const bool more = (kt + 1 < nkv);
        const uint32_t* Vb = sm + ((kt & 1) ? FVS1 : FVS0);

        float sf[8][4];
        #pragma unroll
        for (int t = 0; t < 8; t++)
            #pragma unroll
            for (int j = 0; j < 4; j++) sf[t][j] = 0.0f;

        #pragma unroll
        for (int k = 0; k < 8; k++) {
            uint2 qa = *(const uint2*)&Qs[(mw + g)     * FLDQ + k * 8 + 2 * c4];
            uint2 qb = *(const uint2*)&Qs[(mw + g + 8) * FLDQ + k * 8 + 2 * c4];
            #pragma unroll
            for (int t = 0; t < 8; t++) {
                uint2 kb = *(const uint2*)&Ks[(t * 8 + g) * FLDK + k * 8 + 2 * c4];
                mma_f16(sf[t], qa.x, qb.x, qa.y, qb.y, kb.x, kb.y);
            }
        }

        if (kt >= nkv - 2) {
            const int k0 = kt * 64;
            const int r0 = q0 + mw + g;
            const int r1 = r0 + 8;
            #pragma unroll
            for (int t = 0; t < 8; t++) {
                const int cg0 = k0 + t * 8 + c4 * 2;
                if (cg0     > r0) sf[t][0] = -INFINITY;
                if (cg0 + 1 > r0) sf[t][1] = -INFINITY;
                if (cg0     > r1) sf[t][2] = -INFINITY;
                if (cg0 + 1 > r1) sf[t][3] = -INFINITY;
            }
        }

        __syncthreads();

        if (more) {
            const int kn = (kt + 1) * 64;
            uint32_t* Vn = sm + (((kt + 1) & 1) ? FVS1 : FVS0);
            #pragma unroll
            for (int p = 0; p < 4; p++) {
                int cid = p * 256 + tid;
                int r = cid >> 4, w4 = cid & 15;
                cp_async16(&Ks[r * FLDK + w4 * 4], KH + (kn + r) * 64 + w4 * 4);
            }
            #pragma unroll
            for (int p = 0; p < 4; p++) {
                int cid = p * 256 + tid;
                int vr = cid >> 6, w = cid & 63;
                cp_async16(&Vn[vr * FLDV + w * 4],
                           VH + (kt + 1) * 4096 + vr * 256 + w * 4);
            }
            CP_COMMIT();
        }

        float mx0 = -INFINITY, mx1 = -INFINITY;
        #pragma unroll
        for (int t = 0; t < 8; t++) {
            mx0 = fmaxf(mx0, fmaxf(sf[t][0], sf[t][1]));
            mx1 = fmaxf(mx1, fmaxf(sf[t][2], sf[t][3]));
        }
        mx0 = fmaxf(mx0, __shfl_xor_sync(0xffffffffu, mx0, 1));
        mx0 = fmaxf(mx0, __shfl_xor_sync(0xffffffffu, mx0, 2));
        mx1 = fmaxf(mx1, __shfl_xor_sync(0xffffffffu, mx1, 1));
        mx1 = fmaxf(mx1, __shfl_xor_sync(0xffffffffu, mx1, 2));

        const float mn0 = fmaxf(m0, mx0);
        const float mn1 = fmaxf(m1, mx1);
        const float al0 = exp2f(m0 - mn0);
        const float al1 = exp2f(m1 - mn1);

        float s0 = 0.0f, s1 = 0.0f;
        #pragma unroll
        for (int t = 0; t < 8; t++) {
            sf[t][0] = exp2f(sf[t][0] - mn0);
            sf[t][1] = exp2f(sf[t][1] - mn0);
            sf[t][2] = exp2f(sf[t][2] - mn1);
            sf[t][3] = exp2f(sf[t][3] - mn1);
            s0 += sf[t][0] + sf[t][1];
            s1 += sf[t][2] + sf[t][3];
        }
        s0 += __shfl_xor_sync(0xffffffffu, s0, 1);
        s0 += __shfl_xor_sync(0xffffffffu, s0, 2);
        s1 += __shfl_xor_sync(0xffffffffu, s1, 1);
        s1 += __shfl_xor_sync(0xffffffffu, s1, 2);

        l0 = l0 * al0 + s0;  m0 = mn0;
        l1 = l1 * al1 + s1;  m1 = mn1;

        #pragma unroll
        for (int t = 0; t < 16; t++) {
            of[t][0] *= al0; of[t][1] *= al0;
            of[t][2] *= al1; of[t][3] *= al1;
        }

        #pragma unroll
        for (int kc = 0; kc < 4; kc++) {
            uint32_t a0 = f2h2(sf[2*kc  ][0], sf[2*kc  ][1]);
            uint32_t a1 = f2h2(sf[2*kc  ][2], sf[2*kc  ][3]);
            uint32_t a2 = f2h2(sf[2*kc+1][0], sf[2*kc+1][1]);
            uint32_t a3 = f2h2(sf[2*kc+1][2], sf[2*kc+1][3]);
            #pragma unroll
            for (int t = 0; t < 16; t++) {
                uint2 vb = *(const uint2*)&Vb[(kc * 4 + c4) * FLDV + 2 * (t * 8 + g)];
                mma_f16(of[t], a0, a1, a2, a3, vb.x, vb.y);
            }
        }

        CP_WAIT0();
        __syncthreads();
    }

    const float inv0 = 1.0f / l0;
    const float inv1 = 1.0f / l1;
    const int r0f = q0 + mw + g;
    const int r1f = r0f + 8;
    const int grow0 = hb * 256 + (r0f >> 3);
    const int grow1 = hb * 256 + (r1f >> 3);
    const int cb0 = (r0f & 7) * 8;
    const int cb1 = (r1f & 7) * 8;
    #pragma unroll
    for (int t = 0; t < 16; t++) {
        const int sub = 2 * c4 + (t & 1);
        oh[grow0 * 512 + (cb0 + (t >> 1)) * 8 + sub] = f2h2(of[t][0] * inv0, of[t][1] * inv0);
        oh[grow1 * 512 + (cb1 + (t >> 1)) * 8 + sub] = f2h2(of[t][2] * inv1, of[t][3] * inv1);
    }
}

// ---------------------------------------------------------------------------
// Launch
// ---------------------------------------------------------------------------
extern "C" void kernel_launch(void* const* d_in, const int* in_sizes, int n_in,
                              void* d_out, int out_size)
{
    const float* x    = (const float*)d_in[0];
    const float* qkv  = (const float*)d_in[1];
    const float* proj = (const float*)d_in[2];
    float* out = (float*)d_out;

    uint32_t *xh, *wh, *ph, *qh, *kh, *vp, *vh, *oh;
    cudaGetSymbolAddress((void**)&xh, g_xh);
    cudaGetSymbolAddress((void**)&wh, g_wh);
    cudaGetSymbolAddress((void**)&ph, g_ph);
    cudaGetSymbolAddress((void**)&qh, g_qh);
    cudaGetSymbolAddress((void**)&kh, g_kh);
    cudaGetSymbolAddress((void**)&vp, g_vp);
    cudaGetSymbolAddress((void**)&vh, g_vh);
    cudaGetSymbolAddress((void**)&oh, g_oh);

    convert_all<<<768, 256>>>(x, qkv, proj, xh, wh, ph);

    const int qkv_smem = (64 * 72 + 32 * 264) * (int)sizeof(uint32_t);  // 52,224 B
    cudaFuncSetAttribute(f16_gemm_qkv,
                         cudaFuncAttributeMaxDynamicSharedMemorySize, qkv_smem);
    f16_gemm_qkv<<<dim3(24, 128), 128, qkv_smem>>>(xh, wh, qh, kh, vp);

    convert_v_kernel<<<4096, 256>>>(vp, vh);

    const int flash_smem = FSMEMW * (int)sizeof(uint32_t);  // 89,088 B
    cudaFuncSetAttribute(flash_f16_kernel,
                         cudaFuncAttributeMaxDynamicSharedMemorySize, flash_smem);
    flash_f16_kernel<<<dim3(HEADS, SEQ / 128), 256, flash_smem>>>(qh, kh, vh, oh);

    const int proj_smem = (2 * 128 * 72 + 2 * 32 * 136) * (int)sizeof(uint32_t);
    cudaFuncSetAttribute(f16_gemm_proj,
                         cudaFuncAttributeMaxDynamicSharedMemorySize, proj_smem);
    f16_gemm_proj<<<dim3(2, 64), 256, proj_smem>>>(oh, ph, out);
}